// round 16
// baseline (speedup 1.0000x reference)
#include <cuda_runtime.h>
#include <cstdint>

// Fuzzy min-max composition: out[b,o] = max_i min(m[b,i], clamp(w[i,o],0,1))
// B=1024, IN=512, OUT=256, fp32.
//
// Exact TWO-tier threshold filter (T1=0.9375 ~32 cands, T2=0.875 ~32 more).
// After tier-1 a warp-uniform vote: if all 64 outputs owned by the warp are
// >= T1, every unscanned i has min(m_i,w) <= m_i <= T1 <= c -> exact, skip
// tier-2 (~87% of warps). Same at T2. Below T2 (~1.3 outputs per GRID) or
// on list overflow: exact warp-cooperative full-row scan. Exact for ANY
// input distribution.
//
// Scan uses a cp.async (LDGSTS) RING: 16 candidate w-rows in flight in a
// 16KB smem ring -> zero register cost for latency hiding (R13/R15 showed
// register double-buffering spills at the 72-reg one-wave cap). Each thread
// copies and later consumes ONLY its own 8 bytes per row (outputs 2t,2t+1),
// so ring lanes are thread-private: no barriers, divergence-safe.
// Groups of 2 rows; wait_group 7 guarantees rows k,k+1 landed; rows k+16
// are issued into slots only AFTER rows k,k+1 are consumed (write lands
// ~450cyc after issue -> no WAR hazard on the 29cyc LDS).
// Clamp elimination: accumulators start at 0 and bench m >= 0, so w < 0
// never wins the max; upper clamp subsumed by min with m <= 1.

#define IN_DIM  512
#define OUT_DIM 256
#define THREADS 128
#define NW      4
#define CAP     128           // per tier; mean fill ~32; counts fit 16 bits
#define DEPTH   16            // ring rows in flight (8 groups of 2)
#define T1      0.9375f
#define T2      0.875f
#define FULL    0xFFFFFFFFu

__global__ __launch_bounds__(THREADS, 7)
void fuzzy_minmax_kernel(const float* __restrict__ m,
                         const float* __restrict__ w,
                         float* __restrict__ out)
{
    __shared__ __align__(16) float  s_ring[DEPTH * OUT_DIM];   // 16KB ring
    __shared__ __align__(16) float2 s_t1[CAP + 8];  // {val, int-bits i*OUT_DIM}
    __shared__ __align__(16) float2 s_t2[CAP + 8];
    __shared__ __align__(16) int    s_cnt[NW];      // c1 | c2<<16

    const int b    = blockIdx.x;
    const int t    = threadIdx.x;
    const int lane = t & 31;
    const int wid  = t >> 5;

    // ---- Pass A: row load (float4/thread) + ballot census ----
    const float4 mvv = reinterpret_cast<const float4*>(m + (size_t)b * IN_DIM)[t];
    const float v[4] = {mvv.x, mvv.y, mvv.z, mvv.w};
    unsigned hm[4], qm[4];
    int ch = 0, cq = 0;
    #pragma unroll
    for (int j = 0; j < 4; j++) {
        const unsigned g1 = __ballot_sync(FULL, v[j] > T1);
        const unsigned g2 = __ballot_sync(FULL, v[j] > T2);
        hm[j] = g1;  qm[j] = g2 & ~g1;
        ch += __popc(hm[j]);  cq += __popc(qm[j]);
    }
    if (lane == 0) s_cnt[wid] = ch | (cq << 16);
    __syncthreads();

    // ---- Pass B: packed prefix (1x LDS.128) + candidate placement ----
    const int4 pa = *reinterpret_cast<const int4*>(&s_cnt[0]);
    const int pk[4] = {pa.x, pa.y, pa.z, pa.w};
    int basep = 0, totp = 0;
    #pragma unroll
    for (int ww = 0; ww < NW; ww++) {
        totp += pk[ww];
        if (ww < wid) basep += pk[ww];
    }
    // per-tier sums <= 512 -> no cross-field carry in 16-bit fields
    int o1 = basep & 0xFFFF, o2 = basep >> 16;
    const int tot1 = totp & 0xFFFF, tot2 = totp >> 16;

    const unsigned ltm = (1u << lane) - 1u;
    #pragma unroll
    for (int j = 0; j < 4; j++) {
        const int i = 4 * t + j;
        if (v[j] > T1) {
            const int p = o1 + __popc(hm[j] & ltm);
            if (p < CAP) s_t1[p] = make_float2(v[j], __int_as_float(i * OUT_DIM));
        } else if (v[j] > T2) {
            const int p = o2 + __popc(qm[j] & ltm);
            if (p < CAP) s_t2[p] = make_float2(v[j], __int_as_float(i * OUT_DIM));
        }
        o1 += __popc(hm[j]);  o2 += __popc(qm[j]);
    }
    // sentinel pads (val=0 -> exact no-op; off=0 reads valid w[0..])
    const float2 zz = make_float2(0.f, __int_as_float(0));
    if (t < 8       && tot1 <= CAP) s_t1[tot1 + t]       = zz;
    else if (t < 16 && tot2 <= CAP) s_t2[tot2 + (t - 8)] = zz;
    __syncthreads();

    const bool overflow = (tot1 > CAP) || (tot2 > CAP);
    const int  np1 = overflow ? 0 : (tot1 + 1) & ~1;
    const int  np2 = overflow ? 0 : (tot2 + 1) & ~1;

    const int o   = 2 * t;                    // outputs o, o+1
    const int myb = o;                        // my float index within a row
    const uint32_t ring_u32 =
        (uint32_t)__cvta_generic_to_shared(&s_ring[0]);
    float c0 = 0.f, c1r = 0.f;

    // issue one 2-row group of cp.asyncs (guarded; always commits a group)
    auto issue2 = [&](const float2* lst, int j, int np) {
        if (j < np) {                          // block-uniform condition
            const float4 cj = reinterpret_cast<const float4*>(lst)[j >> 1];
            const float* g0 = w + __float_as_int(cj.y) + myb;
            const float* g1 = w + __float_as_int(cj.w) + myb;
            const uint32_t d0 = ring_u32 + (uint32_t)((( j      & (DEPTH - 1)) * OUT_DIM + myb) * 4);
            const uint32_t d1 = ring_u32 + (uint32_t)((((j + 1) & (DEPTH - 1)) * OUT_DIM + myb) * 4);
            asm volatile("cp.async.ca.shared.global [%0], [%1], 8;" :: "r"(d0), "l"(g0) : "memory");
            asm volatile("cp.async.ca.shared.global [%0], [%1], 8;" :: "r"(d1), "l"(g1) : "memory");
        }
        asm volatile("cp.async.commit_group;" ::: "memory");
    };

    // cp.async ring scan: consume rows k,k+1 then refill slots with k+16,k+17
    auto scan = [&](const float2* lst, int np, float& r0, float& r1) {
        if (np <= 0) return;
        #pragma unroll
        for (int j = 0; j < DEPTH; j += 2) issue2(lst, j, np);   // 8 groups
        float a0 = r0, a1 = r1, d0 = 0.f, d1 = 0.f;
        const float4* q = reinterpret_cast<const float4*>(lst);
        for (int k = 0; k < np; k += 2) {
            asm volatile("cp.async.wait_group 7;" ::: "memory"); // rows k,k+1 landed
            const float4 c = q[k >> 1];
            const float2 w0 = *reinterpret_cast<const float2*>(
                &s_ring[(( k      & (DEPTH - 1)) * OUT_DIM) + myb]);
            const float2 w1 = *reinterpret_cast<const float2*>(
                &s_ring[(((k + 1) & (DEPTH - 1)) * OUT_DIM) + myb]);
            a0 = fmaxf(a0, fminf(c.x, w0.x));  a1 = fmaxf(a1, fminf(c.x, w0.y));
            d0 = fmaxf(d0, fminf(c.z, w1.x));  d1 = fmaxf(d1, fminf(c.z, w1.y));
            issue2(lst, k + DEPTH, np);        // refill freed slots
        }
        asm volatile("cp.async.wait_group 0;" ::: "memory");     // drain (empties)
        r0 = fmaxf(a0, d0);  r1 = fmaxf(a1, d1);
    };

    // ---- tier-1 scan, vote, tier-2 rescue (thread-private ring lanes ->
    //      warp divergence on tier-2 is safe) ----
    scan(s_t1, np1, c0, c1r);
    if (__ballot_sync(FULL, fminf(c0, c1r) >= T1) != FULL) {
        scan(s_t2, np2, c0, c1r);
    }

    // ---- warp-cooperative exact fallback (~1.3 outputs per GRID) ----
    unsigned need0 = __ballot_sync(FULL, overflow || c0  < T2);
    unsigned need1 = __ballot_sync(FULL, overflow || c1r < T2);
    const float* mrow = m + (size_t)b * IN_DIM;
    while (need0 | need1) {                   // warp-uniform loop
        const bool from0 = (need0 != 0);
        unsigned& nd = from0 ? need0 : need1;
        const int L = __ffs(nd) - 1;
        nd &= nd - 1;
        const int ot = __shfl_sync(FULL, from0 ? o : o + 1, L);
        float acc = 0.f;                      // stays >= 0 (max with 0-init)
        #pragma unroll
        for (int r = 0; r < IN_DIM / 32; r++) {
            const int i = lane + 32 * r;
            acc = fmaxf(acc, fminf(mrow[i], w[i * OUT_DIM + ot]));
        }
        // nonneg float order == uint order -> hardware redux
        const unsigned mx = __reduce_max_sync(FULL, __float_as_uint(acc));
        if (lane == L) { if (from0) c0 = __uint_as_float(mx); else c1r = __uint_as_float(mx); }
    }

    float2 res; res.x = c0; res.y = c1r;
    *reinterpret_cast<float2*>(out + (size_t)b * OUT_DIM + o) = res;
}

extern "C" void kernel_launch(void* const* d_in, const int* in_sizes, int n_in,
                              void* d_out, int out_size)
{
    const float* m = (const float*)d_in[0];   // [B, IN] fp32
    const float* w = (const float*)d_in[1];   // [IN, OUT] fp32
    float* out = (float*)d_out;               // [B, OUT] fp32

    const int B = in_sizes[0] / IN_DIM;       // 1024 for the reference shapes
    fuzzy_minmax_kernel<<<B, THREADS>>>(m, w, out);
}

// round 17
// speedup vs baseline: 1.3703x; 1.3703x over previous
#include <cuda_runtime.h>

// Fuzzy min-max composition: out[b,o] = max_i min(m[b,i], clamp(w[i,o],0,1))
// B=1024, IN=512, OUT=256, fp32.
//
// Exact TWO-tier threshold filter (T1=0.9375 ~32 cands, T2=0.875 ~32 more).
// After tier-1 a warp-uniform vote: if all 64 outputs owned by the warp are
// >= T1, every unscanned i has min(m_i,w) <= m_i <= T1 <= c -> exact, skip
// tier-2 (~87% of warps). Same at T2. Below T2 (~1.3 outputs per GRID) or
// on list overflow: exact warp-cooperative full-row scan. Exact for ANY
// input distribution.
//
// Scan: two-stage ping-pong with 4-CANDIDATE stages where each stage's
// GATHERS are issued one stage ahead of consumption. Stage = 2 float4
// candidates + 4 float2 gathers = 16 regs; two stages in flight = 32 regs,
// total ~60 -> fits the 72-reg one-wave cap (R13/R15 spilled with
// 8-candidate stages = 24+ regs each). __launch_bounds__(128,7) keeps
// 7 blocks/SM -> 1024 blocks in ONE wave (28 warps/SM).
// 24 sentinel pads (val=0 -> exact no-op; off=0 reads valid w[0..]) make
// the +16-candidate lookahead unconditional and in-bounds.
// Clamp elimination: accumulators start at 0 and bench m >= 0, so w < 0
// never wins the max; upper clamp subsumed by min with m <= 1.

#define IN_DIM  512
#define OUT_DIM 256
#define THREADS 128
#define NW      4
#define CAP     128           // per tier; mean fill ~32; counts fit 16 bits
#define PAD     24
#define T1      0.9375f
#define T2      0.875f
#define FULL    0xFFFFFFFFu

__global__ __launch_bounds__(THREADS, 7)
void fuzzy_minmax_kernel(const float* __restrict__ m,
                         const float* __restrict__ w,
                         float* __restrict__ out)
{
    __shared__ __align__(16) float2 s_t1[CAP + PAD]; // {val, int-bits i*OUT_DIM}
    __shared__ __align__(16) float2 s_t2[CAP + PAD];
    __shared__ __align__(16) int    s_cnt[NW];       // c1 | c2<<16

    const int b    = blockIdx.x;
    const int t    = threadIdx.x;
    const int lane = t & 31;
    const int wid  = t >> 5;

    // ---- Pass A: row load (float4/thread) + ballot census ----
    const float4 mvv = reinterpret_cast<const float4*>(m + (size_t)b * IN_DIM)[t];
    const float v[4] = {mvv.x, mvv.y, mvv.z, mvv.w};
    unsigned hm[4], qm[4];
    int ch = 0, cq = 0;
    #pragma unroll
    for (int j = 0; j < 4; j++) {
        const unsigned g1 = __ballot_sync(FULL, v[j] > T1);
        const unsigned g2 = __ballot_sync(FULL, v[j] > T2);
        hm[j] = g1;  qm[j] = g2 & ~g1;
        ch += __popc(hm[j]);  cq += __popc(qm[j]);
    }
    if (lane == 0) s_cnt[wid] = ch | (cq << 16);
    __syncthreads();

    // ---- Pass B: packed prefix (1x LDS.128) + candidate placement ----
    const int4 pa = *reinterpret_cast<const int4*>(&s_cnt[0]);
    const int pk[4] = {pa.x, pa.y, pa.z, pa.w};
    int basep = 0, totp = 0;
    #pragma unroll
    for (int ww = 0; ww < NW; ww++) {
        totp += pk[ww];
        if (ww < wid) basep += pk[ww];
    }
    // per-tier sums <= 512 -> no cross-field carry in 16-bit fields
    int o1 = basep & 0xFFFF, o2 = basep >> 16;
    const int tot1 = totp & 0xFFFF, tot2 = totp >> 16;

    const unsigned ltm = (1u << lane) - 1u;
    #pragma unroll
    for (int j = 0; j < 4; j++) {
        const int i = 4 * t + j;
        if (v[j] > T1) {
            const int p = o1 + __popc(hm[j] & ltm);
            if (p < CAP) s_t1[p] = make_float2(v[j], __int_as_float(i * OUT_DIM));
        } else if (v[j] > T2) {
            const int p = o2 + __popc(qm[j] & ltm);
            if (p < CAP) s_t2[p] = make_float2(v[j], __int_as_float(i * OUT_DIM));
        }
        o1 += __popc(hm[j]);  o2 += __popc(qm[j]);
    }
    // 24 sentinel pads per tier (val=0 -> exact no-op; covers round-up to 8
    // AND the +16-candidate gather lookahead)
    const float2 zz = make_float2(0.f, __int_as_float(0));
    if (t < PAD          && tot1 <= CAP) s_t1[tot1 + t]         = zz;
    else if (t < 2 * PAD && tot2 <= CAP) s_t2[tot2 + (t - PAD)] = zz;
    __syncthreads();

    const bool overflow = (tot1 > CAP) || (tot2 > CAP);
    const int  np1 = overflow ? 0 : (tot1 + 7) & ~7;
    const int  np2 = overflow ? 0 : (tot2 + 7) & ~7;

    const int o = 2 * t;                      // outputs o, o+1
    const float* wo = w + o;
    float c0 = 0.f, c1r = 0.f;

    // two-stage ping-pong, 4-candidate stages, gathers issued 1 stage ahead
    auto scan = [&](const float2* lst, int np, float& r0, float& r1) {
        if (np <= 0) return;
        const float4* q = reinterpret_cast<const float4*>(lst);
        float a0 = r0, a1 = r1, d0 = 0.f, d1 = 0.f;
        // stage A: candidates 0..3, gathers issued
        float4 cA0 = q[0], cA1 = q[1];
        float2 wA0 = *reinterpret_cast<const float2*>(wo + __float_as_int(cA0.y));
        float2 wA1 = *reinterpret_cast<const float2*>(wo + __float_as_int(cA0.w));
        float2 wA2 = *reinterpret_cast<const float2*>(wo + __float_as_int(cA1.y));
        float2 wA3 = *reinterpret_cast<const float2*>(wo + __float_as_int(cA1.w));
        // stage B: candidates 4..7, gathers issued
        float4 cB0 = q[2], cB1 = q[3];
        float2 wB0 = *reinterpret_cast<const float2*>(wo + __float_as_int(cB0.y));
        float2 wB1 = *reinterpret_cast<const float2*>(wo + __float_as_int(cB0.w));
        float2 wB2 = *reinterpret_cast<const float2*>(wo + __float_as_int(cB1.y));
        float2 wB3 = *reinterpret_cast<const float2*>(wo + __float_as_int(cB1.w));
        for (int k = 0; k < np; k += 8) {
            const int h = k >> 1;
            // consume stage A (its gathers were issued one stage ago)
            a0 = fmaxf(a0, fminf(cA0.x, wA0.x));  a1 = fmaxf(a1, fminf(cA0.x, wA0.y));
            d0 = fmaxf(d0, fminf(cA0.z, wA1.x));  d1 = fmaxf(d1, fminf(cA0.z, wA1.y));
            a0 = fmaxf(a0, fminf(cA1.x, wA2.x));  a1 = fmaxf(a1, fminf(cA1.x, wA2.y));
            d0 = fmaxf(d0, fminf(cA1.z, wA3.x));  d1 = fmaxf(d1, fminf(cA1.z, wA3.y));
            // refill stage A with candidates k+8..k+11 (pad-safe), issue gathers
            cA0 = q[h + 4];  cA1 = q[h + 5];
            wA0 = *reinterpret_cast<const float2*>(wo + __float_as_int(cA0.y));
            wA1 = *reinterpret_cast<const float2*>(wo + __float_as_int(cA0.w));
            wA2 = *reinterpret_cast<const float2*>(wo + __float_as_int(cA1.y));
            wA3 = *reinterpret_cast<const float2*>(wo + __float_as_int(cA1.w));
            // consume stage B
            a0 = fmaxf(a0, fminf(cB0.x, wB0.x));  a1 = fmaxf(a1, fminf(cB0.x, wB0.y));
            d0 = fmaxf(d0, fminf(cB0.z, wB1.x));  d1 = fmaxf(d1, fminf(cB0.z, wB1.y));
            a0 = fmaxf(a0, fminf(cB1.x, wB2.x));  a1 = fmaxf(a1, fminf(cB1.x, wB2.y));
            d0 = fmaxf(d0, fminf(cB1.z, wB3.x));  d1 = fmaxf(d1, fminf(cB1.z, wB3.y));
            // refill stage B with candidates k+12..k+15 (pad-safe)
            cB0 = q[h + 6];  cB1 = q[h + 7];
            wB0 = *reinterpret_cast<const float2*>(wo + __float_as_int(cB0.y));
            wB1 = *reinterpret_cast<const float2*>(wo + __float_as_int(cB0.w));
            wB2 = *reinterpret_cast<const float2*>(wo + __float_as_int(cB1.y));
            wB3 = *reinterpret_cast<const float2*>(wo + __float_as_int(cB1.w));
        }
        r0 = fmaxf(a0, d0);  r1 = fmaxf(a1, d1);
    };

    // ---- tier-1 scan, vote, tier-2 rescue ----
    scan(s_t1, np1, c0, c1r);
    if (__ballot_sync(FULL, fminf(c0, c1r) >= T1) != FULL) {
        scan(s_t2, np2, c0, c1r);
    }

    // ---- warp-cooperative exact fallback (~1.3 outputs per GRID) ----
    unsigned need0 = __ballot_sync(FULL, overflow || c0  < T2);
    unsigned need1 = __ballot_sync(FULL, overflow || c1r < T2);
    const float* mrow = m + (size_t)b * IN_DIM;
    while (need0 | need1) {                   // warp-uniform loop
        const bool from0 = (need0 != 0);
        unsigned& nd = from0 ? need0 : need1;
        const int L = __ffs(nd) - 1;
        nd &= nd - 1;
        const int ot = __shfl_sync(FULL, from0 ? o : o + 1, L);
        float acc = 0.f;                      // stays >= 0 (max with 0-init)
        #pragma unroll
        for (int r = 0; r < IN_DIM / 32; r++) {
            const int i = lane + 32 * r;
            acc = fmaxf(acc, fminf(mrow[i], w[i * OUT_DIM + ot]));
        }
        // nonneg float order == uint order -> hardware redux
        const unsigned mx = __reduce_max_sync(FULL, __float_as_uint(acc));
        if (lane == L) { if (from0) c0 = __uint_as_float(mx); else c1r = __uint_as_float(mx); }
    }

    float2 res; res.x = c0; res.y = c1r;
    *reinterpret_cast<float2*>(out + (size_t)b * OUT_DIM + o) = res;
}

extern "C" void kernel_launch(void* const* d_in, const int* in_sizes, int n_in,
                              void* d_out, int out_size)
{
    const float* m = (const float*)d_in[0];   // [B, IN] fp32
    const float* w = (const float*)d_in[1];   // [IN, OUT] fp32
    float* out = (float*)d_out;               // [B, OUT] fp32

    const int B = in_sizes[0] / IN_DIM;       // 1024 for the reference shapes
    fuzzy_minmax_kernel<<<B, THREADS>>>(m, w, out);
}